// round 15
// baseline (speedup 1.0000x reference)
#include <cuda_runtime.h>

#define NEL 16777216   // B*C*D*H*W
typedef unsigned long long u64;

// Scratch: q/k/v in attention layout [b][s][head][d][e].
__device__ __align__(16) float g_q[NEL];
__device__ __align__(16) float g_k[NEL];
__device__ __align__(16) float g_v[NEL];

__device__ __forceinline__ u64 pk2(float lo, float hi) {
    u64 r; asm("mov.b64 %0, {%1,%2};" : "=l"(r) : "f"(lo), "f"(hi)); return r;
}
__device__ __forceinline__ float2 upk2(u64 v) {
    float2 r; asm("mov.b64 {%0,%1}, %2;" : "=f"(r.x), "=f"(r.y) : "l"(v)); return r;
}
__device__ __forceinline__ u64 addx2(u64 a, u64 b) {
    u64 r; asm("add.rn.f32x2 %0, %1, %2;" : "=l"(r) : "l"(a), "l"(b)); return r;
}
#define FMA2(d, a, b) asm("fma.rn.f32x2 %0, %1, %2, %0;" : "+l"(d) : "l"(a), "l"(b))

// ---------------------------------------------------------------------------
// W[64][64] ([o][k]) -> two conflict-free planes, 16B stride over ot. (proven)
// ---------------------------------------------------------------------------
__device__ __forceinline__ void stage_W2(float* A, float* B,
                                         const float* __restrict__ Wsrc) {
    for (int idx = threadIdx.x; idx < 2048; idx += 256) {
        int k = idx >> 5, t = idx & 31;
        int ot = t >> 2, j = t & 3;
        A[idx] = Wsrc[(ot*8 + j)*64 + k];
        B[idx] = Wsrc[(ot*8 + 4 + j)*64 + k];
    }
}

__device__ __forceinline__ void stage_chunk(float* xs, const float* __restrict__ xsrc,
                                            int b, int n0, int kc) {
    const float4* xg = (const float4*)(xsrc + (u64)b*8388608 + n0);
    float4* xs4 = (float4*)xs;
    #pragma unroll
    for (int i = 0; i < 8; i++) {
        int idx = threadIdx.x + i*256;
        int c = idx >> 6, n4 = idx & 63;
        xs4[c*64 + n4] = xg[(u64)(kc*32 + c)*32768 + n4];
    }
}

// ---------------------------------------------------------------------------
// Q/K/V projection (proven, unchanged). dst selected device-side.
// ---------------------------------------------------------------------------
__global__ void __launch_bounds__(256, 2) k_proj(const float* __restrict__ x,
                                                 const float* __restrict__ W,
                                                 int which)
{
    __shared__ __align__(16) float xs[32*256];
    __shared__ __align__(16) float WA[2048];
    __shared__ __align__(16) float WB[2048];
    float* dst = (which == 0) ? g_q : (which == 1) ? g_k : g_v;
    int b = blockIdx.x >> 9;
    int n0 = (blockIdx.x & 511) << 8;
    stage_W2(WA, WB, W);

    int ot = threadIdx.x & 7, nt = threadIdx.x >> 3;
    u64 acc[8][4];
    #pragma unroll
    for (int o = 0; o < 8; o++)
        #pragma unroll
        for (int np = 0; np < 4; np++) acc[o][np] = 0ull;

    #pragma unroll 1
    for (int kc = 0; kc < 2; kc++) {
        __syncthreads();
        stage_chunk(xs, x, b, n0, kc);
        __syncthreads();
        #pragma unroll 4
        for (int k = 0; k < 32; k++) {
            int kg = kc*32 + k;
            float4 wa = *(const float4*)&WA[kg*32 + ot*4];
            float4 wb = *(const float4*)&WB[kg*32 + ot*4];
            u64 ws[8] = {pk2(wa.x,wa.x), pk2(wa.y,wa.y), pk2(wa.z,wa.z), pk2(wa.w,wa.w),
                         pk2(wb.x,wb.x), pk2(wb.y,wb.y), pk2(wb.z,wb.z), pk2(wb.w,wb.w)};
            const ulonglong2* xp = (const ulonglong2*)&xs[k*256 + nt*8];
            ulonglong2 x0 = xp[0], x1 = xp[1];
            u64 xv[4] = {x0.x, x0.y, x1.x, x1.y};
            #pragma unroll
            for (int o = 0; o < 8; o++)
                #pragma unroll
                for (int np = 0; np < 4; np++)
                    FMA2(acc[o][np], ws[o], xv[np]);
        }
    }

    int d = n0 >> 12;
    int sb = (n0 & 4095) + nt*8;
    float* gq = dst + (u64)b*8388608 + ot*256 + d*8;
    #pragma unroll
    for (int np = 0; np < 4; np++) {
        float2 f[8];
        #pragma unroll
        for (int o = 0; o < 8; o++) f[o] = upk2(acc[o][np]);
        float* p0 = gq + (u64)(sb + 2*np)*2048;
        ((float4*)p0)[0] = make_float4(f[0].x, f[1].x, f[2].x, f[3].x);
        ((float4*)p0)[1] = make_float4(f[4].x, f[5].x, f[6].x, f[7].x);
        float* p1 = gq + (u64)(sb + 2*np + 1)*2048;
        ((float4*)p1)[0] = make_float4(f[0].y, f[1].y, f[2].y, f[3].y);
        ((float4*)p1)[1] = make_float4(f[4].y, f[5].y, f[6].y, f[7].y);
    }
}

// ---------------------------------------------------------------------------
// Fused attention + O projection, 2-D lane-tiled main loop.
// Block = (b, 8 s, all 8 heads), 512 threads; warp w: sw=w&7, hh=w>>3,
// 4 heads hh*4..+3. Lane = (dg 0..7, jg 0..3) owns [4d x 8j] of sim;
// partials combined across jg via shfl butterfly; lane writes d = dg*4+jg.
// ctx -> sctx[c][d*12+sw]; then proven GEMM epilogue applies Wo -> out.
// smem floats: ks 16*272 | vs 16*272 | qs 16*352 | sctx 64*384 | WT 4096.
// ---------------------------------------------------------------------------
__global__ void __launch_bounds__(512) k_attn_o(const float* __restrict__ Wo,
                                                float* __restrict__ out)
{
    extern __shared__ __align__(16) float sm[];
    int tid = threadIdx.x;
    int warp = tid >> 5, lane = tid & 31;
    float* ksw  = sm + warp*272;                 // [jg-block:68][j:8][e]
    float* vsw  = sm + 4352 + warp*272;
    float* qsw  = sm + 8704 + warp*352;          // [dg-block:44][r:8]
    float* sctx = sm + 14336;                    // [c][d*12 + sw]
    float* WT   = sm + 38912;                    // WT[k*64 + o]

    int sw = warp & 7, hh = warp >> 3;
    int blk = blockIdx.x;
    int s8 = blk & 511, b = blk >> 9;
    int s = s8*8 + sw;

    for (int idx = tid; idx < 4096; idx += 512)
        WT[idx] = Wo[(idx & 63)*64 + (idx >> 6)];

    const float CEXP = 0.35355339059327373f * 1.4426950408889634f;
    int dg = lane >> 2, jg = lane & 3;

    #pragma unroll 1
    for (int hi = 0; hi < 4; hi++) {
        int head = hh*4 + hi;
        u64 u = (u64)(((b << 12) + s)*8 + head);

        __syncwarp();   // prior iteration's smem reads complete
        {
            const float4* kp = (const float4*)(g_k + u*256);
            const float4* vp = (const float4*)(g_v + u*256);
            const float4* qp = (const float4*)(g_q + u*256);
            int j0 = lane >> 1, h = lane & 1, j1 = j0 + 16;
            *(float4*)&ksw[(j0>>3)*68 + (j0&7)*8 + h*4] = kp[lane];
            *(float4*)&ksw[(j1>>3)*68 + (j1&7)*8 + h*4] = kp[lane + 32];
            *(float4*)&vsw[(j0>>3)*68 + (j0&7)*8 + h*4] = vp[lane];
            *(float4*)&vsw[(j1>>3)*68 + (j1&7)*8 + h*4] = vp[lane + 32];
            *(float4*)&qsw[(j0>>2)*44 + (j0&3)*8 + h*4] = qp[lane];
            *(float4*)&qsw[(j1>>2)*44 + (j1&3)*8 + h*4] = qp[lane + 32];
        }
        __syncwarp();

        // q rows dg*4 .. dg*4+3
        u64 q[4][4];
        #pragma unroll
        for (int r = 0; r < 4; r++) {
            const ulonglong2* p = (const ulonglong2*)&qsw[dg*44 + r*8];
            ulonglong2 a = p[0], c = p[1];
            q[r][0] = a.x; q[r][1] = a.y; q[r][2] = c.x; q[r][3] = c.y;
        }

        float ss[4] = {0.f, 0.f, 0.f, 0.f};
        u64 acc[4][4];
        #pragma unroll
        for (int r = 0; r < 4; r++)
            #pragma unroll
            for (int c = 0; c < 4; c++) acc[r][c] = 0ull;

        #pragma unroll
        for (int j = 0; j < 8; j++) {
            const ulonglong2* kq = (const ulonglong2*)&ksw[jg*68 + j*8];
            ulonglong2 ka = kq[0], kb = kq[1];
            const ulonglong2* vq = (const ulonglong2*)&vsw[jg*68 + j*8];
            ulonglong2 va = vq[0], vb = vq[1];
            #pragma unroll
            for (int r = 0; r < 4; r++) {
                u64 a0 = 0ull, a1 = 0ull;
                FMA2(a0, ka.x, q[r][0]); FMA2(a1, ka.y, q[r][1]);
                FMA2(a0, kb.x, q[r][2]); FMA2(a1, kb.y, q[r][3]);
                float2 f0 = upk2(a0), f1 = upk2(a1);
                float p = exp2f(((f0.x + f0.y) + (f1.x + f1.y)) * CEXP);
                ss[r] += p;
                u64 pp = pk2(p, p);
                FMA2(acc[r][0], va.x, pp); FMA2(acc[r][1], va.y, pp);
                FMA2(acc[r][2], vb.x, pp); FMA2(acc[r][3], vb.y, pp);
            }
        }

        // combine partials across the 4 jg-lanes (xor 1, xor 2)
        u64 s01 = pk2(ss[0], ss[1]), s23 = pk2(ss[2], ss[3]);
        #pragma unroll
        for (int m = 1; m <= 2; m <<= 1) {
            s01 = addx2(s01, __shfl_xor_sync(0xffffffffu, s01, m));
            s23 = addx2(s23, __shfl_xor_sync(0xffffffffu, s23, m));
            #pragma unroll
            for (int r = 0; r < 4; r++)
                #pragma unroll
                for (int c = 0; c < 4; c++)
                    acc[r][c] = addx2(acc[r][c], __shfl_xor_sync(0xffffffffu, acc[r][c], m));
        }

        // lane owns d-row dg*4 + jg: its r = jg slice holds full totals
        int d = dg*4 + jg;
        float2 sA = upk2(s01), sB = upk2(s23);
        float ssv = (jg == 0) ? sA.x : (jg == 1) ? sA.y : (jg == 2) ? sB.x : sB.y;
        float inv = 1.f / ssv;
        float2 r0 = upk2(acc[jg][0]), r1 = upk2(acc[jg][1]);
        float2 r2 = upk2(acc[jg][2]), r3 = upk2(acc[jg][3]);
        float vals[8] = {r0.x*inv, r0.y*inv, r1.x*inv, r1.y*inv,
                         r2.x*inv, r2.y*inv, r3.x*inv, r3.y*inv};
        #pragma unroll
        for (int e = 0; e < 8; e++)
            sctx[(head*8 + e)*384 + d*12 + sw] = vals[e];
    }
    __syncthreads();

    // ---- epilogue GEMM (proven): out[64 c][256 loc] = Wo x ctx, K=64 ----
    {
        int ot = tid & 15, nt = tid >> 4;
        u64 acc[4][4];
        #pragma unroll
        for (int o = 0; o < 4; o++)
            #pragma unroll
            for (int np = 0; np < 4; np++) acc[o][np] = 0ull;

        #pragma unroll 4
        for (int k = 0; k < 64; k++) {
            float4 wt = *(const float4*)&WT[k*64 + ot*4];
            u64 ws[4] = {pk2(wt.x,wt.x), pk2(wt.y,wt.y), pk2(wt.z,wt.z), pk2(wt.w,wt.w)};
            const float4* xp = (const float4*)&sctx[k*384 + nt*12];
            float4 xa = xp[0], xb = xp[1];
            u64 xv[4] = {pk2(xa.x,xa.y), pk2(xa.z,xa.w), pk2(xb.x,xb.y), pk2(xb.z,xb.w)};
            #pragma unroll
            for (int o = 0; o < 4; o++)
                #pragma unroll
                for (int np = 0; np < 4; np++)
                    FMA2(acc[o][np], ws[o], xv[np]);
        }

        float* ob = out + (u64)b*8388608 + nt*4096 + s8*8;
        #pragma unroll
        for (int o = 0; o < 4; o++) {
            float* oc = ob + (u64)(ot*4 + o)*131072;
            float2 a0 = upk2(acc[o][0]), a1 = upk2(acc[o][1]);
            float2 a2 = upk2(acc[o][2]), a3 = upk2(acc[o][3]);
            ((float4*)oc)[0] = make_float4(a0.x, a0.y, a1.x, a1.y);
            ((float4*)oc)[1] = make_float4(a2.x, a2.y, a3.x, a3.y);
        }
    }
}

extern "C" void kernel_launch(void* const* d_in, const int* in_sizes, int n_in,
                              void* d_out, int out_size)
{
    const float* qf = (const float*)d_in[0];
    const float* kf = (const float*)d_in[1];
    const float* Wq = (const float*)d_in[2];
    const float* Wk = (const float*)d_in[3];
    const float* Wv = (const float*)d_in[4];
    const float* Wo = (const float*)d_in[5];
    float* out = (float*)d_out;

    const int ATTN_SMEM = 43008 * 4;   // 168 KB dynamic shared
    cudaFuncSetAttribute(k_attn_o, cudaFuncAttributeMaxDynamicSharedMemorySize,
                         ATTN_SMEM);

    k_proj  <<<1024, 256>>>(qf, Wq, 0);
    k_proj  <<<1024, 256>>>(kf, Wk, 1);
    k_proj  <<<1024, 256>>>(kf, Wv, 2);
    k_attn_o<<<1024, 512, ATTN_SMEM>>>(Wo, out);
}